// round 6
// baseline (speedup 1.0000x reference)
#include <cuda_runtime.h>
#include <math.h>

// Problem shape (fixed by the reference)
#define NSAMP 2048
#define OBS   48
// Layers: (out, in)
// L0: 512 x 48   L1: 256 x 512   L2: 128 x 256   L3: 12 x 128

// Inter-layer activation scratch (device globals: allocation-free).
__device__ __align__(16) float g_a0[NSAMP * 512];
__device__ __align__(16) float g_a1[NSAMP * 256];

__device__ __forceinline__ float elu(float s) {
    return (s > 0.0f) ? s : (__expf(s) - 1.0f);
}

// ---------------------------------------------------------------------------
// L0: obs-normalization fused with 512x48 layer. 256 threads, 16-lane groups
// (48 floats = 12 float4 per row), 128 rows per CTA -> 4 CTAs per sample.
// ---------------------------------------------------------------------------
__global__ void __launch_bounds__(256, 8)
k_l0(const float* __restrict__ obs, const float* __restrict__ mean,
     const float* __restrict__ stdv, const float* __restrict__ W0,
     const float* __restrict__ b0) {
    const int b  = blockIdx.x;
    const int n  = b >> 2;             // sample
    const int rb = (b & 3) * 128;      // row base within sample
    const int tid = threadIdx.x;

    __shared__ __align__(16) float xs[OBS];
    if (tid < OBS) {
        const int i = n * OBS + tid;
        float v = (obs[i] - mean[i]) / stdv[i];
        xs[tid] = fminf(fmaxf(v, -5.0f), 5.0f);
    }
    __syncthreads();

    const int gid = tid >> 4;          // 16 groups of 16 lanes
    const int gl  = tid & 15;
    const float4* __restrict__ xv = reinterpret_cast<const float4*>(xs);
    const float* __restrict__ W = W0 + (size_t)n * 512 * 48;
    const float* __restrict__ bb = b0 + (size_t)n * 512;
    float* __restrict__ y = g_a0 + (size_t)n * 512;

    #pragma unroll
    for (int r0 = rb + gid; r0 < rb + 128; r0 += 32) {
        const int r1 = r0 + 16;
        float bias0 = __ldcs(bb + r0);
        float bias1 = __ldcs(bb + r1);
        const float4* __restrict__ Wr0 =
            reinterpret_cast<const float4*>(W + (size_t)r0 * 48);
        const float4* __restrict__ Wr1 =
            reinterpret_cast<const float4*>(W + (size_t)r1 * 48);
        float s0 = 0.0f, s1 = 0.0f;
        if (gl < 12) {                 // 12 float4 per row, 16 lanes
            float4 w0 = __ldcs(Wr0 + gl);
            float4 w1 = __ldcs(Wr1 + gl);
            float4 v  = xv[gl];
            s0 = fmaf(w0.x, v.x, fmaf(w0.y, v.y, fmaf(w0.z, v.z, w0.w * v.w)));
            s1 = fmaf(w1.x, v.x, fmaf(w1.y, v.y, fmaf(w1.z, v.z, w1.w * v.w)));
        }
        #pragma unroll
        for (int o = 8; o >= 1; o >>= 1) {
            s0 += __shfl_xor_sync(0xffffffffu, s0, o);
            s1 += __shfl_xor_sync(0xffffffffu, s1, o);
        }
        if (gl == 0) {
            y[r0] = elu(s0 + bias0);
            y[r1] = elu(s1 + bias1);
        }
    }
}

// ---------------------------------------------------------------------------
// L1: 256 x 512. 256 threads (8 warps), warp per row-pair, 32 rows/CTA
// -> 8 CTAs per sample (fine-grained for work-steal balance).
// ---------------------------------------------------------------------------
__global__ void __launch_bounds__(256, 8)
k_l1(const float* __restrict__ Wg, const float* __restrict__ bg,
     const float* __restrict__ xg, float* __restrict__ yg) {
    constexpr int IN = 512, NV = IN / 4;
    const int b  = blockIdx.x;
    const int n  = b >> 3;
    const int rb = (b & 7) * 32;
    const int tid = threadIdx.x;
    const int wid = tid >> 5;          // 8 warps
    const int gl  = tid & 31;

    __shared__ __align__(16) float xs[IN];
    {
        const float4* __restrict__ src =
            reinterpret_cast<const float4*>(xg + (size_t)n * IN);
        if (tid < NV) reinterpret_cast<float4*>(xs)[tid] = src[tid];
    }
    __syncthreads();

    const float4* __restrict__ xv = reinterpret_cast<const float4*>(xs);
    const float* __restrict__ W = Wg + (size_t)n * 256 * IN;
    const float* __restrict__ bb = bg + (size_t)n * 256;
    float* __restrict__ y = yg + (size_t)n * 256;

    #pragma unroll
    for (int r0 = rb + wid; r0 < rb + 32; r0 += 16) {
        const int r1 = r0 + 8;
        float bias0 = __ldcs(bb + r0);
        float bias1 = __ldcs(bb + r1);
        const float4* __restrict__ Wr0 =
            reinterpret_cast<const float4*>(W + (size_t)r0 * IN);
        const float4* __restrict__ Wr1 =
            reinterpret_cast<const float4*>(W + (size_t)r1 * IN);
        float s0 = 0.0f, s1 = 0.0f;
        #pragma unroll
        for (int j = gl; j < NV; j += 32) {
            float4 w0 = __ldcs(Wr0 + j);
            float4 w1 = __ldcs(Wr1 + j);
            float4 v  = xv[j];
            s0 = fmaf(w0.x, v.x, s0);
            s0 = fmaf(w0.y, v.y, s0);
            s0 = fmaf(w0.z, v.z, s0);
            s0 = fmaf(w0.w, v.w, s0);
            s1 = fmaf(w1.x, v.x, s1);
            s1 = fmaf(w1.y, v.y, s1);
            s1 = fmaf(w1.z, v.z, s1);
            s1 = fmaf(w1.w, v.w, s1);
        }
        #pragma unroll
        for (int o = 16; o >= 1; o >>= 1) {
            s0 += __shfl_xor_sync(0xffffffffu, s0, o);
            s1 += __shfl_xor_sync(0xffffffffu, s1, o);
        }
        if (gl == 0) {
            y[r0] = elu(s0 + bias0);
            y[r1] = elu(s1 + bias1);
        }
    }
}

// ---------------------------------------------------------------------------
// L2 (128x256) fused with L3 (12x128) + tanh. One CTA (128 thr) per sample.
// L2 result stays in shared memory; L3 reads it directly.
// ---------------------------------------------------------------------------
__global__ void __launch_bounds__(128, 16)
k_l23(const float* __restrict__ W2, const float* __restrict__ b2,
      const float* __restrict__ W3, const float* __restrict__ b3,
      float* __restrict__ out) {
    constexpr int IN2 = 256, NV2 = IN2 / 4;   // 64
    const int n = blockIdx.x;
    const int tid = threadIdx.x;
    const int wid = tid >> 5;          // 4 warps
    const int gl  = tid & 31;

    __shared__ __align__(16) float xs[IN2];
    __shared__ __align__(16) float h[128];
    {
        const float4* __restrict__ src =
            reinterpret_cast<const float4*>(g_a1 + (size_t)n * IN2);
        if (tid < NV2) reinterpret_cast<float4*>(xs)[tid] = src[tid];
    }
    __syncthreads();

    // ---- L2: 128 rows, warp per row-pair ----
    {
        const float4* __restrict__ xv = reinterpret_cast<const float4*>(xs);
        const float* __restrict__ W = W2 + (size_t)n * 128 * IN2;
        const float* __restrict__ bb = b2 + (size_t)n * 128;
        #pragma unroll
        for (int r0 = wid; r0 < 128; r0 += 8) {
            const int r1 = r0 + 4;
            float bias0 = __ldcs(bb + r0);
            float bias1 = __ldcs(bb + r1);
            const float4* __restrict__ Wr0 =
                reinterpret_cast<const float4*>(W + (size_t)r0 * IN2);
            const float4* __restrict__ Wr1 =
                reinterpret_cast<const float4*>(W + (size_t)r1 * IN2);
            float s0 = 0.0f, s1 = 0.0f;
            #pragma unroll
            for (int j = gl; j < NV2; j += 32) {
                float4 w0 = __ldcs(Wr0 + j);
                float4 w1 = __ldcs(Wr1 + j);
                float4 v  = xv[j];
                s0 = fmaf(w0.x, v.x, s0);
                s0 = fmaf(w0.y, v.y, s0);
                s0 = fmaf(w0.z, v.z, s0);
                s0 = fmaf(w0.w, v.w, s0);
                s1 = fmaf(w1.x, v.x, s1);
                s1 = fmaf(w1.y, v.y, s1);
                s1 = fmaf(w1.z, v.z, s1);
                s1 = fmaf(w1.w, v.w, s1);
            }
            #pragma unroll
            for (int o = 16; o >= 1; o >>= 1) {
                s0 += __shfl_xor_sync(0xffffffffu, s0, o);
                s1 += __shfl_xor_sync(0xffffffffu, s1, o);
            }
            if (gl == 0) {
                h[r0] = elu(s0 + bias0);
                h[r1] = elu(s1 + bias1);
            }
        }
    }
    __syncthreads();

    // ---- L3: 12 x 128 + tanh ----
    {
        const float4* __restrict__ hv = reinterpret_cast<const float4*>(h);
        const float* __restrict__ W = W3 + (size_t)n * 12 * 128;
        const float* __restrict__ bb = b3 + (size_t)n * 12;
        #pragma unroll
        for (int row = wid; row < 12; row += 4) {
            float bias = __ldcs(bb + row);
            const float4* __restrict__ Wr =
                reinterpret_cast<const float4*>(W + (size_t)row * 128);
            float4 w = __ldcs(Wr + gl);
            float4 v = hv[gl];
            float s = fmaf(w.x, v.x, fmaf(w.y, v.y, fmaf(w.z, v.z, w.w * v.w)));
            #pragma unroll
            for (int o = 16; o >= 1; o >>= 1)
                s += __shfl_xor_sync(0xffffffffu, s, o);
            if (gl == 0)
                out[n * 12 + row] = tanhf(s + bias);
        }
    }
}

extern "C" void kernel_launch(void* const* d_in, const int* in_sizes, int n_in,
                              void* d_out, int out_size) {
    const float* obs  = (const float*)d_in[0];
    const float* mean = (const float*)d_in[1];
    const float* stdv = (const float*)d_in[2];
    const float* W0   = (const float*)d_in[3];
    const float* b0   = (const float*)d_in[4];
    const float* W1   = (const float*)d_in[5];
    const float* b1   = (const float*)d_in[6];
    const float* W2   = (const float*)d_in[7];
    const float* b2   = (const float*)d_in[8];
    const float* W3   = (const float*)d_in[9];
    const float* b3   = (const float*)d_in[10];
    float* out = (float*)d_out;

    float* a0;  cudaGetSymbolAddress((void**)&a0, g_a0);
    float* a1;  cudaGetSymbolAddress((void**)&a1, g_a1);

    // L0: 4 CTAs/sample
    k_l0<<<NSAMP * 4, 256>>>(obs, mean, stdv, W0, b0);
    // L1: 8 CTAs/sample
    k_l1<<<NSAMP * 8, 256>>>(W1, b1, a0, a1);
    // L2+L3 fused: 1 CTA/sample
    k_l23<<<NSAMP, 128>>>(W2, b2, W3, b3, out);
}